// round 15
// baseline (speedup 1.0000x reference)
#include <cuda_runtime.h>

// Signature-kernel MMD — skewed-parallelogram PDE (useful-work-only).
// Lane L owns fine rows 4L+1..4L+4; at step t it computes column j=t-L+1.
// 157 steps, 4 real cells/lane/step, ONE shfl/step (lane L-1's row-4L value).
// inc table: 64 rows x 63 (row v = coarse row v, row 63 = junk pad), folded
// values 0.25*inc-1. Activation: c*=1/shp=1 at t==L (32-step prologue only).
// Lane-0 up-value forced to 1 (K[0,*]=1). Garbage provably never consumed.
// WPC=2 -> 32256 B/CTA -> 7 CTAs/SM, 14 warps/SM, one wave.

#define BSZ 32
#define LEN 64
#define NTRI ((BSZ*(BSZ+1))/2)     // 528
#define NTASKS (2*NTRI + BSZ*BSZ)  // 2080
#define WPC 2
#define NBLK (NTASKS / WPC)        // 1040

#define RSF 63                     // row stride (floats), gap-free
#define WFLOATS (64*RSF)           // 4032 floats = 16128 B per task

#define NEG_HALF_LOG2E (-0.72134752044448170368f)   // -0.5 * log2(e)

__device__ float g_partial[NTASKS];
__device__ unsigned int g_count;   // zero-init; reducer re-arms

__global__ void __launch_bounds__(32*WPC, 7)
sig_kernel(const float* __restrict__ x, const float* __restrict__ y,
           float* __restrict__ out)
{
    extern __shared__ __align__(16) float smem[];
    const int lane = threadIdx.x & 31;
    const int wid  = threadIdx.x >> 5;
    const int task = blockIdx.x * WPC + wid;

    float* tab = smem + wid * WFLOATS;    // rows 0..62 real, row 63 junk pad

    // ---- decode task -> pair pointers + weight ----
    const float *pa, *pb;
    float weight;
    {
        int t = task;
        if (t < 2*NTRI) {
            const float* base = (t < NTRI) ? x : y;
            if (t >= NTRI) t -= NTRI;
            int a = 0;
            while (t >= (BSZ - a)) { t -= (BSZ - a); ++a; }
            int b = a + t;
            pa = base + a*(LEN*4);
            pb = base + b*(LEN*4);
            weight = (a == b ? 1.0f : 2.0f) * (1.0f/1024.0f);
        } else {
            t -= 2*NTRI;
            pa = x + (t >> 5)*(LEN*4);
            pb = y + (t & 31)*(LEN*4);
            weight = -2.0f/1024.0f;
        }
    }

    // ---- streaming RBF gram + folded second differences (fp32) ----
    // Writes tab[v*63 + c] = 0.25*inc_coarse(v,c) - 1 for v,c in 0..62.
    const int j0 = lane << 1;
    const float4 b0 = __ldg(reinterpret_cast<const float4*>(pb + 4*j0));
    const float4 b1 = __ldg(reinterpret_cast<const float4*>(pb + 4*j0 + 4));

    float g0p, g1p;
    {
        float4 a = __ldg(reinterpret_cast<const float4*>(pa));
        float d0x=a.x-b0.x, d0y=a.y-b0.y, d0z=a.z-b0.z, d0w=a.w-b0.w;
        float d1x=a.x-b1.x, d1y=a.y-b1.y, d1z=a.z-b1.z, d1w=a.w-b1.w;
        g0p = exp2f(NEG_HALF_LOG2E*(d0x*d0x + d0y*d0y + d0z*d0z + d0w*d0w));
        g1p = exp2f(NEG_HALF_LOG2E*(d1x*d1x + d1y*d1y + d1z*d1z + d1w*d1w));
    }
    #pragma unroll 4
    for (int u = 1; u < LEN; ++u) {
        float4 a = __ldg(reinterpret_cast<const float4*>(pa + 4*u));
        float d0x=a.x-b0.x, d0y=a.y-b0.y, d0z=a.z-b0.z, d0w=a.w-b0.w;
        float d1x=a.x-b1.x, d1y=a.y-b1.y, d1z=a.z-b1.z, d1w=a.w-b1.w;
        float g0 = exp2f(NEG_HALF_LOG2E*(d0x*d0x + d0y*d0y + d0z*d0z + d0w*d0w));
        float g1 = exp2f(NEG_HALF_LOG2E*(d1x*d1x + d1y*d1y + d1z*d1z + d1w*d1w));
        float t0 = g0 - g0p;
        float t1 = g1 - g1p;
        float tn = __shfl_down_sync(0xffffffffu, t0, 1);
        float r0 = fmaf(0.25f, t1 - t0, -1.0f);
        float r1 = fmaf(0.25f, tn - t1, -1.0f);
        float* row = tab + (u - 1) * RSF;
        row[j0] = r0;                              // cols 0..62
        if (lane != 31) row[j0 + 1] = r1;          // col 63 doesn't exist
        g0p = g0; g1p = g1;
    }
    __syncwarp();

    // ---- skewed-parallelogram Goursat sweep ----
    // State: c1..c4 = K(4L+1..4L+4, j-1), shp = K(4L, j-1), v4 = K(4L+4, j_last).
    // Per step: sh = shfl_up(v4) [lane0 -> 1], a0 = inc row 2L, a1 = row 2L+1
    // at col (j-1)>>1; v1 = fma(a0,shp,sh)+c1; v2 = fma(a0,c1,v1)+c2;
    // v3 = fma(a1,c2,v2)+c3; v4 = fma(a1,c3,v3)+c4.
    const int L = lane;
    const bool isL0 = (L == 0);
    const float* tabL = tab + 126*L;      // row 2L base; +63 = row 2L+1 (L=31: junk row)

    float c1 = 1.f, c2 = 1.f, c3 = 1.f, c4 = 1.f, shp = 1.f, v4 = 0.f;

    // Phase A: t = 0..31 (activation window)
    #pragma unroll
    for (int t = 0; t < 32; ++t) {
        float sh = __shfl_up_sync(0xffffffffu, v4, 1);
        if (isL0) sh = 1.f;
        if (t == L) { c1 = c2 = c3 = c4 = 1.f; shp = 1.f; }  // left boundary j=0
        int idx = (t - L) >> 1;               // arithmetic shift; in-region
        float a0 = tabL[idx];
        float a1 = tabL[idx + 63];
        float v1 = fmaf(a0, shp, sh) + c1;
        float v2 = fmaf(a0, c1, v1) + c2;
        float v3 = fmaf(a1, c2, v2) + c3;
        float w4 = fmaf(a1, c3, v3) + c4;
        c1 = v1; c2 = v2; c3 = v3; c4 = w4; shp = sh; v4 = w4;
    }

    // Phase B: t = 32..155, two steps per body (s = 16..77), all lanes active.
    // idx(2s) = s + d0, idx(2s+1) = s + d0 + (L&1), d0 = -((L+1)>>1).
    const float* qa = tabL + ((32 - L) >> 1);        // idx at t=32
    const float* qb = qa + (L & 1);                  // idx at t=33
    #pragma unroll 2
    for (int s = 16; s < 78; ++s) {
        // substep 0 (t = 2s)
        float sh = __shfl_up_sync(0xffffffffu, v4, 1);
        if (isL0) sh = 1.f;
        float a0 = qa[0], a1 = qa[63];
        float v1 = fmaf(a0, shp, sh) + c1;
        float v2 = fmaf(a0, c1, v1) + c2;
        float v3 = fmaf(a1, c2, v2) + c3;
        float w4 = fmaf(a1, c3, v3) + c4;
        // substep 1 (t = 2s+1)
        float sh2 = __shfl_up_sync(0xffffffffu, w4, 1);
        if (isL0) sh2 = 1.f;
        float e0 = qb[0], e1 = qb[63];
        float u1 = fmaf(e0, sh, sh2) + v1;
        float u2 = fmaf(e0, v1, u1) + v2;
        float u3 = fmaf(e1, v2, u2) + v3;
        float u4 = fmaf(e1, v3, u3) + w4;
        c1 = u1; c2 = u2; c3 = u3; c4 = u4; shp = sh2; v4 = u4;
        ++qa; ++qb;
    }

    // Final step t = 156 (substep-0 pattern, s = 78): only v2 of lane 31 needed.
    float res;
    {
        float sh = __shfl_up_sync(0xffffffffu, v4, 1);
        if (isL0) sh = 1.f;
        float a0 = qa[0];
        float v1 = fmaf(a0, shp, sh) + c1;
        float v2 = fmaf(a0, c1, v1) + c2;     // K(126,126) on lane 31
        res = __shfl_sync(0xffffffffu, v2, 31);
    }
    if (lane == 0) g_partial[task] = res * weight;

    // ---- last-block deterministic reduction (dynamic smem only) ----
    __threadfence();
    __syncthreads();
    unsigned int* ticket_slot = reinterpret_cast<unsigned int*>(smem);
    if (threadIdx.x == 0) *ticket_slot = atomicAdd(&g_count, 1u);
    __syncthreads();
    if (*ticket_slot == (unsigned)(gridDim.x - 1)) {
        double s = 0.0;
        for (int i = threadIdx.x; i < NTASKS; i += 32*WPC)
            s += (double)__ldcg(&g_partial[i]);
        double* ds = reinterpret_cast<double*>(smem + 64);
        ds[threadIdx.x] = s;
        __syncthreads();
        for (int w = (32*WPC)/2; w > 0; w >>= 1) {
            if (threadIdx.x < w) ds[threadIdx.x] += ds[threadIdx.x + w];
            __syncthreads();
        }
        if (threadIdx.x == 0) {
            out[0] = (float)ds[0];
            g_count = 0;                 // re-arm for next graph replay
        }
    }
}

extern "C" void kernel_launch(void* const* d_in, const int* in_sizes, int n_in,
                              void* d_out, int out_size)
{
    const float* x = (const float*)d_in[0];
    const float* y = (const float*)d_in[1];
    (void)in_sizes; (void)n_in; (void)out_size;

    cudaFuncSetAttribute(sig_kernel,
                         cudaFuncAttributePreferredSharedMemoryCarveout, 100);

    const size_t shmem = (size_t)WPC * WFLOATS * sizeof(float);  // 32256 B
    sig_kernel<<<NBLK, 32*WPC, shmem>>>(x, y, (float*)d_out);
}

// round 16
// speedup vs baseline: 1.0071x; 1.0071x over previous
#include <cuda_runtime.h>

// Signature-kernel MMD — skewed-parallelogram PDE + conflict-free O/E layout.
// Lane L owns fine rows 4L+1..4L+4, sweeps columns skewed by lane; 157 steps,
// 1 shfl + 2 LDS + 8 FMA-class ops per step, useful-work-only.
// Table: R12 layout — [guard 4 | O: odd coarse rows 1..61, 31x63 | E: even
// rows 0..62, 32x63], folded values 0.25*inc-1. Lane L reads E row L (a0) and
// O row L (a1), lane step 63 == 31 mod 32 (odd) -> zero bank conflicts.
// Gram via norm trick: arg = fma(log2e, dot, C*na + C*nb), exp2f.
// WPC=2 -> 31808 B/CTA -> 7 CTAs/SM, 14 warps/SM, one wave.

#define BSZ 32
#define LEN 64
#define NTRI ((BSZ*(BSZ+1))/2)     // 528
#define NTASKS (2*NTRI + BSZ*BSZ)  // 2080
#define WPC 2
#define NBLK (NTASKS / WPC)        // 1040

#define RSF 63
#define GUARDF 4
#define OSZF (31*RSF)              // 1953
#define WFLOATS 3976               // 15904 B per task (7 CTAs/SM proven)

#define CEXP (-0.72134752044448170368f)   // -0.5 * log2(e)
#define LOG2E (1.44269504088896340736f)   // -2 * CEXP

__device__ float g_partial[NTASKS];
__device__ unsigned int g_count;   // zero-init; reducer re-arms

__global__ void __launch_bounds__(32*WPC, 7)
sig_kernel(const float* __restrict__ x, const float* __restrict__ y,
           float* __restrict__ out)
{
    extern __shared__ __align__(16) float smem[];
    const int lane = threadIdx.x & 31;
    const int wid  = threadIdx.x >> 5;
    const int task = blockIdx.x * WPC + wid;

    float* warpbase = smem + wid * WFLOATS;
    float* Ob = warpbase + GUARDF;        // odd coarse rows 1,3,..,61
    float* Eb = Ob + OSZF;                // even coarse rows 0,2,..,62

    // Zero guard + tail pad (all PDE-readable bytes otherwise gram-written
    // or provably in-region junk consumed only by garbage cells).
    if (lane == 0) {
        reinterpret_cast<uint4*>(warpbase)[0]   = make_uint4(0u,0u,0u,0u);
        reinterpret_cast<uint4*>(warpbase)[993] = make_uint4(0u,0u,0u,0u);
    }

    // ---- decode task -> pair pointers + weight ----
    const float *pa, *pb;
    float weight;
    {
        int t = task;
        if (t < 2*NTRI) {
            const float* base = (t < NTRI) ? x : y;
            if (t >= NTRI) t -= NTRI;
            int a = 0;
            while (t >= (BSZ - a)) { t -= (BSZ - a); ++a; }
            int b = a + t;
            pa = base + a*(LEN*4);
            pb = base + b*(LEN*4);
            weight = (a == b ? 1.0f : 2.0f) * (1.0f/1024.0f);
        } else {
            t -= 2*NTRI;
            pa = x + (t >> 5)*(LEN*4);
            pb = y + (t & 31)*(LEN*4);
            weight = -2.0f/1024.0f;
        }
    }

    // ---- streaming RBF gram (norm trick) + folded second differences ----
    const int j0 = lane << 1;
    const float4 b0 = __ldg(reinterpret_cast<const float4*>(pb + 4*j0));
    const float4 b1 = __ldg(reinterpret_cast<const float4*>(pb + 4*j0 + 4));
    const float Cnb0 = CEXP*(b0.x*b0.x + b0.y*b0.y + b0.z*b0.z + b0.w*b0.w);
    const float Cnb1 = CEXP*(b1.x*b1.x + b1.y*b1.y + b1.z*b1.z + b1.w*b1.w);

    float g0p, g1p;
    {
        float4 a = __ldg(reinterpret_cast<const float4*>(pa));
        float Cna = CEXP*(a.x*a.x + a.y*a.y + a.z*a.z + a.w*a.w);
        float d0 = a.x*b0.x; d0 = fmaf(a.y,b0.y,d0); d0 = fmaf(a.z,b0.z,d0); d0 = fmaf(a.w,b0.w,d0);
        float d1 = a.x*b1.x; d1 = fmaf(a.y,b1.y,d1); d1 = fmaf(a.z,b1.z,d1); d1 = fmaf(a.w,b1.w,d1);
        g0p = exp2f(fmaf(LOG2E, d0, Cna + Cnb0));
        g1p = exp2f(fmaf(LOG2E, d1, Cna + Cnb1));
    }
    #pragma unroll 4
    for (int u = 1; u < LEN; ++u) {
        float4 a = __ldg(reinterpret_cast<const float4*>(pa + 4*u));
        float Cna = CEXP*(a.x*a.x + a.y*a.y + a.z*a.z + a.w*a.w);
        float d0 = a.x*b0.x; d0 = fmaf(a.y,b0.y,d0); d0 = fmaf(a.z,b0.z,d0); d0 = fmaf(a.w,b0.w,d0);
        float d1 = a.x*b1.x; d1 = fmaf(a.y,b1.y,d1); d1 = fmaf(a.z,b1.z,d1); d1 = fmaf(a.w,b1.w,d1);
        float g0 = exp2f(fmaf(LOG2E, d0, Cna + Cnb0));
        float g1 = exp2f(fmaf(LOG2E, d1, Cna + Cnb1));
        float t0 = g0 - g0p;
        float t1 = g1 - g1p;
        float tn = __shfl_down_sync(0xffffffffu, t0, 1);
        float r0 = fmaf(0.25f, t1 - t0, -1.0f);    // folded: 0.25*inc - 1
        float r1 = fmaf(0.25f, tn - t1, -1.0f);
        int v = u - 1;
        float* row = ((v & 1) ? Ob : Eb) + (v >> 1) * RSF;
        row[j0] = r0;
        if (lane != 31) row[j0 + 1] = r1;
        g0p = g0; g1p = g1;
    }
    __syncwarp();

    // ---- skewed-parallelogram Goursat sweep (R15 math, O/E addressing) ----
    // a0 = coarse row 2L   -> E region row L:  pA = Eb + 63L
    // a1 = coarse row 2L+1 -> O region row L:  pO = Ob + 63L
    //   (lane 31: pO points past O into E -> finite junk, consumed only by
    //    garbage cells v3/v4 [fine rows 127,128])
    const int L = lane;
    const bool isL0 = (L == 0);
    const float* pA = Eb + 63*L;
    const float* pO = Ob + 63*L;

    float c1 = 1.f, c2 = 1.f, c3 = 1.f, c4 = 1.f, shp = 1.f, v4 = 0.f;

    // Phase A: t = 0..31 (activation window; idx >= -16 stays in-region)
    #pragma unroll
    for (int t = 0; t < 32; ++t) {
        float sh = __shfl_up_sync(0xffffffffu, v4, 1);
        if (isL0) sh = 1.f;
        if (t == L) { c1 = c2 = c3 = c4 = 1.f; shp = 1.f; }  // left boundary j=0
        int idx = (t - L) >> 1;
        float a0 = pA[idx];
        float a1 = pO[idx];
        float v1 = fmaf(a0, shp, sh) + c1;
        float v2 = fmaf(a0, c1, v1) + c2;
        float v3 = fmaf(a1, c2, v2) + c3;
        float w4 = fmaf(a1, c3, v3) + c4;
        c1 = v1; c2 = v2; c3 = v3; c4 = w4; shp = sh; v4 = w4;
    }

    // Phase B: t = 32..155, two substeps per body iteration.
    const int db = L & 1;
    const float* qa  = pA + ((32 - L) >> 1);
    const float* qo  = pO + ((32 - L) >> 1);
    const float* qab = qa + db;
    const float* qob = qo + db;
    #pragma unroll 2
    for (int s = 16; s < 78; ++s) {
        // substep 0 (t = 2s)
        float sh = __shfl_up_sync(0xffffffffu, v4, 1);
        if (isL0) sh = 1.f;
        float a0 = qa[0], a1 = qo[0];
        float v1 = fmaf(a0, shp, sh) + c1;
        float v2 = fmaf(a0, c1, v1) + c2;
        float v3 = fmaf(a1, c2, v2) + c3;
        float w4 = fmaf(a1, c3, v3) + c4;
        // substep 1 (t = 2s+1)
        float sh2 = __shfl_up_sync(0xffffffffu, w4, 1);
        if (isL0) sh2 = 1.f;
        float e0 = qab[0], e1 = qob[0];
        float u1 = fmaf(e0, sh, sh2) + v1;
        float u2 = fmaf(e0, v1, u1) + v2;
        float u3 = fmaf(e1, v2, u2) + v3;
        float u4 = fmaf(e1, v3, u3) + w4;
        c1 = u1; c2 = u2; c3 = u3; c4 = u4; shp = sh2; v4 = u4;
        ++qa; ++qo; ++qab; ++qob;
    }

    // Final step t = 156: only v2 of lane 31 (= K(126,126)) is needed.
    float res;
    {
        float sh = __shfl_up_sync(0xffffffffu, v4, 1);
        if (isL0) sh = 1.f;
        float a0 = qa[0];
        float v1 = fmaf(a0, shp, sh) + c1;
        float v2 = fmaf(a0, c1, v1) + c2;
        res = __shfl_sync(0xffffffffu, v2, 31);
    }
    if (lane == 0) g_partial[task] = res * weight;

    // ---- last-block deterministic reduction (dynamic smem only) ----
    __threadfence();
    __syncthreads();
    unsigned int* ticket_slot = reinterpret_cast<unsigned int*>(smem);
    if (threadIdx.x == 0) *ticket_slot = atomicAdd(&g_count, 1u);
    __syncthreads();
    if (*ticket_slot == (unsigned)(gridDim.x - 1)) {
        double s = 0.0;
        for (int i = threadIdx.x; i < NTASKS; i += 32*WPC)
            s += (double)__ldcg(&g_partial[i]);
        double* ds = reinterpret_cast<double*>(smem + 64);
        ds[threadIdx.x] = s;
        __syncthreads();
        for (int w = (32*WPC)/2; w > 0; w >>= 1) {
            if (threadIdx.x < w) ds[threadIdx.x] += ds[threadIdx.x + w];
            __syncthreads();
        }
        if (threadIdx.x == 0) {
            out[0] = (float)ds[0];
            g_count = 0;                 // re-arm for next graph replay
        }
    }
}

extern "C" void kernel_launch(void* const* d_in, const int* in_sizes, int n_in,
                              void* d_out, int out_size)
{
    const float* x = (const float*)d_in[0];
    const float* y = (const float*)d_in[1];
    (void)in_sizes; (void)n_in; (void)out_size;

    cudaFuncSetAttribute(sig_kernel,
                         cudaFuncAttributePreferredSharedMemoryCarveout, 100);

    const size_t shmem = (size_t)WPC * WFLOATS * sizeof(float);  // 31808 B
    sig_kernel<<<NBLK, 32*WPC, shmem>>>(x, y, (float*)d_out);
}

// round 17
// speedup vs baseline: 1.0316x; 1.0243x over previous
#include <cuda_runtime.h>

// Signature-kernel MMD — skew-2 pipelined parallelogram sweep.
// Lane L owns fine rows 4L+1..4L+4 and runs TWO steps behind lane L-1, so the
// inter-lane shfl value is consumed one full step after issue: the per-step
// critical path is the bare 4-FMA chain (32 cyc), shfl/LDS latency hidden.
// Even/odd column pairs share one coarse-inc index for ALL lanes -> 2 LDS +
// 2 SHFL + 16 FMA per 2 columns. 188 steps (94 pairs). Table: O/E split,
// stride 63 (lane step odd -> conflict-free), folded 0.25*inc-1 values.
// WPC=2 -> 31808 B/CTA -> 7 CTAs/SM, 14 warps/SM, one wave.

#define BSZ 32
#define LEN 64
#define NTRI ((BSZ*(BSZ+1))/2)     // 528
#define NTASKS (2*NTRI + BSZ*BSZ)  // 2080
#define WPC 2
#define NBLK (NTASKS / WPC)        // 1040

#define RSF 63
#define GUARDF 4
#define OSZF (31*RSF)              // 1953
#define WFLOATS 3976               // 15904 B per task (7 CTAs/SM proven)

#define CEXP (-0.72134752044448170368f)   // -0.5 * log2(e)
#define LOG2E (1.44269504088896340736f)

__device__ float g_partial[NTASKS];
__device__ unsigned int g_count;   // zero-init; reducer re-arms

__global__ void __launch_bounds__(32*WPC, 7)
sig_kernel(const float* __restrict__ x, const float* __restrict__ y,
           float* __restrict__ out)
{
    extern __shared__ __align__(16) float smem[];
    const int lane = threadIdx.x & 31;
    const int wid  = threadIdx.x >> 5;
    const int task = blockIdx.x * WPC + wid;

    float* warpbase = smem + wid * WFLOATS;
    float* Ob = warpbase + GUARDF;        // odd coarse rows 1,3,..,61
    float* Eb = Ob + OSZF;                // even coarse rows 0,2,..,62

    if (lane == 0) {                      // guard+pad (insurance; not read)
        reinterpret_cast<uint4*>(warpbase)[0]   = make_uint4(0u,0u,0u,0u);
        reinterpret_cast<uint4*>(warpbase)[993] = make_uint4(0u,0u,0u,0u);
    }

    // ---- decode task -> pair pointers + weight ----
    const float *pa, *pb;
    float weight;
    {
        int t = task;
        if (t < 2*NTRI) {
            const float* base = (t < NTRI) ? x : y;
            if (t >= NTRI) t -= NTRI;
            int a = 0;
            while (t >= (BSZ - a)) { t -= (BSZ - a); ++a; }
            int b = a + t;
            pa = base + a*(LEN*4);
            pb = base + b*(LEN*4);
            weight = (a == b ? 1.0f : 2.0f) * (1.0f/1024.0f);
        } else {
            t -= 2*NTRI;
            pa = x + (t >> 5)*(LEN*4);
            pb = y + (t & 31)*(LEN*4);
            weight = -2.0f/1024.0f;
        }
    }

    // ---- streaming RBF gram (norm trick) + folded second differences ----
    const int j0 = lane << 1;
    const float4 b0 = __ldg(reinterpret_cast<const float4*>(pb + 4*j0));
    const float4 b1 = __ldg(reinterpret_cast<const float4*>(pb + 4*j0 + 4));
    const float Cnb0 = CEXP*(b0.x*b0.x + b0.y*b0.y + b0.z*b0.z + b0.w*b0.w);
    const float Cnb1 = CEXP*(b1.x*b1.x + b1.y*b1.y + b1.z*b1.z + b1.w*b1.w);

    float g0p, g1p;
    {
        float4 a = __ldg(reinterpret_cast<const float4*>(pa));
        float Cna = CEXP*(a.x*a.x + a.y*a.y + a.z*a.z + a.w*a.w);
        float d0 = a.x*b0.x; d0 = fmaf(a.y,b0.y,d0); d0 = fmaf(a.z,b0.z,d0); d0 = fmaf(a.w,b0.w,d0);
        float d1 = a.x*b1.x; d1 = fmaf(a.y,b1.y,d1); d1 = fmaf(a.z,b1.z,d1); d1 = fmaf(a.w,b1.w,d1);
        g0p = exp2f(fmaf(LOG2E, d0, Cna + Cnb0));
        g1p = exp2f(fmaf(LOG2E, d1, Cna + Cnb1));
    }
    #pragma unroll 4
    for (int u = 1; u < LEN; ++u) {
        float4 a = __ldg(reinterpret_cast<const float4*>(pa + 4*u));
        float Cna = CEXP*(a.x*a.x + a.y*a.y + a.z*a.z + a.w*a.w);
        float d0 = a.x*b0.x; d0 = fmaf(a.y,b0.y,d0); d0 = fmaf(a.z,b0.z,d0); d0 = fmaf(a.w,b0.w,d0);
        float d1 = a.x*b1.x; d1 = fmaf(a.y,b1.y,d1); d1 = fmaf(a.z,b1.z,d1); d1 = fmaf(a.w,b1.w,d1);
        float g0 = exp2f(fmaf(LOG2E, d0, Cna + Cnb0));
        float g1 = exp2f(fmaf(LOG2E, d1, Cna + Cnb1));
        float t0 = g0 - g0p;
        float t1 = g1 - g1p;
        float tn = __shfl_down_sync(0xffffffffu, t0, 1);
        float r0 = fmaf(0.25f, t1 - t0, -1.0f);
        float r1 = fmaf(0.25f, tn - t1, -1.0f);
        int v = u - 1;
        float* row = ((v & 1) ? Ob : Eb) + (v >> 1) * RSF;
        row[j0] = r0;
        if (lane != 31) row[j0 + 1] = r1;
        g0p = g0; g1p = g1;
    }
    __syncwarp();

    // ---- skew-2 pipelined Goursat sweep ----
    // Pair s handles columns j0=2s-2L+1, j1=j0+1 (same coarse idx s-L for all
    // lanes). Queue: shp=K[4L,j0-1], sh_use=K[4L,j0]; each shfl delivers the
    // NEXT step's up-value (consumed one full step after issue).
    const int L = lane;
    const bool isL0 = (L == 0);
    const float* qa = Eb + 62*L;          // pA - L  (coarse row 2L)
    const float* qo = Ob + 62*L;          // pO - L  (coarse row 2L+1)

    float c1=1.f, c2=1.f, c3=1.f, c4=1.f, shp=1.f, sh_use=1.f, v4=0.f;

#define PAIR(ACT)                                                       \
    {                                                                   \
        float r = __shfl_up_sync(0xffffffffu, v4, 1);                   \
        if (isL0) r = 1.f;                                              \
        ACT                                                             \
        float a0 = qa[0], a1 = qo[0];                                   \
        float v1 = fmaf(a0, shp, sh_use) + c1;                          \
        float v2 = fmaf(a0, c1, v1) + c2;                               \
        float v3 = fmaf(a1, c2, v2) + c3;                               \
        float w4 = fmaf(a1, c3, v3) + c4;                               \
        float r2 = __shfl_up_sync(0xffffffffu, w4, 1);                  \
        if (isL0) r2 = 1.f;                                             \
        float u1 = fmaf(a0, sh_use, r) + v1;                            \
        float u2 = fmaf(a0, v1, u1) + v2;                               \
        float u3 = fmaf(a1, v2, u2) + v3;                               \
        float u4 = fmaf(a1, v3, u3) + w4;                               \
        c1 = u1; c2 = u2; c3 = u3; c4 = u4; v4 = u4;                    \
        shp = r; sh_use = r2;                                           \
        ++qa; ++qo;                                                     \
    }

    // Phase A: pairs 0..31 (activation: lane L resets at pair s==L, column 1)
    #pragma unroll 8
    for (int s = 0; s < 32; ++s)
        PAIR( if (s == L) { c1=c2=c3=c4=1.f; shp=1.f; } )
    // Phase B: pairs 32..93 (all lanes active or harmless-garbage)
    #pragma unroll 2
    for (int s = 32; s < 94; ++s)
        PAIR( )
#undef PAIR

    // K(126,126) = row 4*31+2 at column 126 = c2 on lane 31 after pair 93.
    float res = __shfl_sync(0xffffffffu, c2, 31);
    if (lane == 0) g_partial[task] = res * weight;

    // ---- last-block deterministic reduction (dynamic smem only) ----
    __threadfence();
    __syncthreads();
    unsigned int* ticket_slot = reinterpret_cast<unsigned int*>(smem);
    if (threadIdx.x == 0) *ticket_slot = atomicAdd(&g_count, 1u);
    __syncthreads();
    if (*ticket_slot == (unsigned)(gridDim.x - 1)) {
        double s = 0.0;
        for (int i = threadIdx.x; i < NTASKS; i += 32*WPC)
            s += (double)__ldcg(&g_partial[i]);
        double* ds = reinterpret_cast<double*>(smem + 64);
        ds[threadIdx.x] = s;
        __syncthreads();
        for (int w = (32*WPC)/2; w > 0; w >>= 1) {
            if (threadIdx.x < w) ds[threadIdx.x] += ds[threadIdx.x + w];
            __syncthreads();
        }
        if (threadIdx.x == 0) {
            out[0] = (float)ds[0];
            g_count = 0;                 // re-arm for next graph replay
        }
    }
}

extern "C" void kernel_launch(void* const* d_in, const int* in_sizes, int n_in,
                              void* d_out, int out_size)
{
    const float* x = (const float*)d_in[0];
    const float* y = (const float*)d_in[1];
    (void)in_sizes; (void)n_in; (void)out_size;

    cudaFuncSetAttribute(sig_kernel,
                         cudaFuncAttributePreferredSharedMemoryCarveout, 100);

    const size_t shmem = (size_t)WPC * WFLOATS * sizeof(float);  // 31808 B
    sig_kernel<<<NBLK, 32*WPC, shmem>>>(x, y, (float*)d_out);
}